// round 13
// baseline (speedup 1.0000x reference)
#include <cuda_runtime.h>
#include <cuda_bf16.h>
#include <cstdint>

// Problem constants: N=50000 nodes, E=1.6M edges, D_in=D_out=128.
#define D 128
#define D4 (D / 4)
#define MAX_NODES 50048          // 391 * 128
#define CAP 128                  // bucket capacity (Poisson(32); overflow astronomically rare)
#define K_TOT 256                // concat [feat ; mean_neigh]

// GEMM smem: 4 tiles [128 rows][272 B] + bias
#define ROWB      272            // 128 bf16 = 256B payload + 16B pad
#define TILE_B    (128 * ROWB)   // 34816
#define SM_AH     0
#define SM_AL     (SM_AH + TILE_B)
#define SM_BH     (SM_AL + TILE_B)
#define SM_BL     (SM_BH + TILE_B)
#define SM_BIAS   (SM_BL + TILE_B)
#define SM_TOTAL  (SM_BIAS + 512)          // 139776 B

// ---------------- scratch (device globals; no allocation allowed) ----------------
__device__ __nv_bfloat16 g_zh[MAX_NODES * K_TOT];   // Z hi  [node][k] (k<128 feat, k>=128 mean)
__device__ __nv_bfloat16 g_zl[MAX_NODES * K_TOT];   // Z lo residual
__device__ __nv_bfloat16 g_wh[D * K_TOT];           // Wcat hi [o][k]
__device__ __nv_bfloat16 g_wl[D * K_TOT];           // Wcat lo residual
__device__ int           g_cnt[MAX_NODES];
__device__ int           g_bucket[MAX_NODES * CAP];

// ---------------- helpers ----------------
__device__ __forceinline__ void mma_bf16(float* d, const unsigned* a, const unsigned* b) {
    asm volatile(
        "mma.sync.aligned.m16n8k16.row.col.f32.bf16.bf16.f32 "
        "{%0,%1,%2,%3}, {%4,%5,%6,%7}, {%8,%9}, {%0,%1,%2,%3};"
        : "+f"(d[0]), "+f"(d[1]), "+f"(d[2]), "+f"(d[3])
        : "r"(a[0]), "r"(a[1]), "r"(a[2]), "r"(a[3]), "r"(b[0]), "r"(b[1]));
}
__device__ __forceinline__ void addf32x2(unsigned long long& acc, unsigned long long a) {
    asm("add.rn.f32x2 %0, %0, %1;" : "+l"(acc) : "l"(a));
}
__device__ __forceinline__ void unpack2(unsigned long long v, float& lo, float& hi) {
    asm("mov.b64 {%0, %1}, %2;" : "=f"(lo), "=f"(hi) : "l"(v));
}
// Two bf16 in a uint32 -> packed f32x2 (exact widen: shift / mask)
__device__ __forceinline__ unsigned long long bf2_to_f32x2(unsigned int v) {
    unsigned long long r;
    asm("{\n\t"
        ".reg .b32 lo, hi;\n\t"
        "shl.b32 lo, %1, 16;\n\t"
        "and.b32 hi, %1, 0xFFFF0000;\n\t"
        "mov.b64 %0, {lo, hi};\n\t"
        "}" : "=l"(r) : "r"(v));
    return r;
}

// ---------------- kernel: zero in-degree counters (incl. pad rows) ----------------
__global__ void zero_kernel() {
    int i = blockIdx.x * blockDim.x + threadIdx.x;
    if (i < MAX_NODES) g_cnt[i] = 0;
}

// ---------------- kernel: feat -> (zh, zl) first half; pad rows zeroed ----------------
__global__ void convert_kernel(const float* __restrict__ feat, int n_f2) {
    int i = blockIdx.x * blockDim.x + threadIdx.x;      // float2 units, 64 per feat-half row
    if (i >= MAX_NODES * 64) return;
    int node = i >> 6;
    int c2   = i & 63;
    __nv_bfloat162* zh2 = reinterpret_cast<__nv_bfloat162*>(g_zh);
    __nv_bfloat162* zl2 = reinterpret_cast<__nv_bfloat162*>(g_zl);
    int idx = node * 128 + c2;                          // bf162 units; full row = 128 bf162
    if (i < n_f2) {
        float2 f = reinterpret_cast<const float2*>(feat)[i];
        __nv_bfloat16 hx = __float2bfloat16_rn(f.x);
        __nv_bfloat16 hy = __float2bfloat16_rn(f.y);
        zh2[idx] = __halves2bfloat162(hx, hy);
        zl2[idx] = __floats2bfloat162_rn(f.x - __bfloat162float(hx),
                                         f.y - __bfloat162float(hy));
    } else {
        __nv_bfloat162 z = __floats2bfloat162_rn(0.f, 0.f);
        zh2[idx] = z; zl2[idx] = z;
    }
}

// ---------------- kernel: weight hi/lo split, [o][k] concat layout ----------------
__global__ void prepw_kernel(const float* __restrict__ W_self,
                             const float* __restrict__ W_neigh) {
    int i = blockIdx.x * blockDim.x + threadIdx.x;      // 0 .. 32767
    if (i >= D * K_TOT) return;
    int o = i >> 8;
    int k = i & 255;
    float w = (k < D) ? W_self[o * D + k] : W_neigh[o * D + (k - D)];
    __nv_bfloat16 h = __float2bfloat16_rn(w);
    g_wh[i] = h;
    g_wl[i] = __float2bfloat16_rn(w - __bfloat162float(h));
}

// ---------------- kernel: fill per-dst buckets (8 edges/thread, MLP=8) ----------------
__global__ void fill_kernel(const int* __restrict__ src,
                            const int* __restrict__ dst,
                            int n_edges) {
    int g = blockIdx.x * blockDim.x + threadIdx.x;
    int e0 = g * 8;
    if (e0 >= n_edges) return;
    if (e0 + 7 < n_edges) {
        int4 sa = *reinterpret_cast<const int4*>(src + e0);
        int4 sb = *reinterpret_cast<const int4*>(src + e0 + 4);
        int4 da = *reinterpret_cast<const int4*>(dst + e0);
        int4 db = *reinterpret_cast<const int4*>(dst + e0 + 4);
        // 8 independent atomic->store chains in flight
        int p0 = atomicAdd(&g_cnt[da.x], 1);
        int p1 = atomicAdd(&g_cnt[da.y], 1);
        int p2 = atomicAdd(&g_cnt[da.z], 1);
        int p3 = atomicAdd(&g_cnt[da.w], 1);
        int p4 = atomicAdd(&g_cnt[db.x], 1);
        int p5 = atomicAdd(&g_cnt[db.y], 1);
        int p6 = atomicAdd(&g_cnt[db.z], 1);
        int p7 = atomicAdd(&g_cnt[db.w], 1);
        if (p0 < CAP) g_bucket[da.x * CAP + p0] = sa.x;
        if (p1 < CAP) g_bucket[da.y * CAP + p1] = sa.y;
        if (p2 < CAP) g_bucket[da.z * CAP + p2] = sa.z;
        if (p3 < CAP) g_bucket[da.w * CAP + p3] = sa.w;
        if (p4 < CAP) g_bucket[db.x * CAP + p4] = sb.x;
        if (p5 < CAP) g_bucket[db.y * CAP + p5] = sb.y;
        if (p6 < CAP) g_bucket[db.z * CAP + p6] = sb.z;
        if (p7 < CAP) g_bucket[db.w * CAP + p7] = sb.w;
    } else {
        for (int e = e0; e < n_edges; e++) {
            int ss = src[e], dd = dst[e];
            int pos = atomicAdd(&g_cnt[dd], 1);
            if (pos < CAP) g_bucket[dd * CAP + pos] = ss;
        }
    }
}

// ---------------- kernel: warp-per-node pull aggregation ----------------
// R8 loop structure; decode via exact shl/and into packed f32x2 accumulators.
__global__ void aggregate_kernel(int n_nodes) {
    int w = (blockIdx.x * blockDim.x + threadIdx.x) >> 5;
    if (w >= MAX_NODES) return;
    int lane = threadIdx.x & 31;

    int c = g_cnt[w];                       // 0 for pad rows
    if (c > CAP) return;                    // handled exactly by fallback kernel

    unsigned long long acc01 = 0ull, acc23 = 0ull;   // packed sums for lane's 4 cols
    const uint2* fb = reinterpret_cast<const uint2*>(g_zh);  // row = 64 uint2; feat half = first 32
    const int* bk = &g_bucket[w * CAP];
    for (int i0 = 0; i0 < c; i0 += 32) {
        int take = min(32, c - i0);
        int my = (lane < take) ? bk[i0 + lane] : 0;
        #pragma unroll 4
        for (int j = 0; j < take; j++) {
            int s = __shfl_sync(0xffffffffu, my, j);
            uint2 v = __ldg(&fb[(size_t)s * 64 + lane]);     // 4 bf16 cols at 4*lane
            addf32x2(acc01, bf2_to_f32x2(v.x));
            addf32x2(acc23, bf2_to_f32x2(v.y));
        }
    }

    float inv = 1.0f / fmaxf((float)c, 1.0f);
    float m0, m1, m2, m3;
    unpack2(acc01, m0, m1);
    unpack2(acc23, m2, m3);
    m0 *= inv; m1 *= inv; m2 *= inv; m3 *= inv;

    __nv_bfloat16 h0 = __float2bfloat16_rn(m0);
    __nv_bfloat16 h1 = __float2bfloat16_rn(m1);
    __nv_bfloat16 h2 = __float2bfloat16_rn(m2);
    __nv_bfloat16 h3 = __float2bfloat16_rn(m3);
    __nv_bfloat162 hA = __halves2bfloat162(h0, h1);
    __nv_bfloat162 hB = __halves2bfloat162(h2, h3);
    __nv_bfloat162 lA = __floats2bfloat162_rn(m0 - __bfloat162float(h0),
                                              m1 - __bfloat162float(h1));
    __nv_bfloat162 lB = __floats2bfloat162_rn(m2 - __bfloat162float(h2),
                                              m3 - __bfloat162float(h3));
    uint2* zh = reinterpret_cast<uint2*>(g_zh);
    uint2* zl = reinterpret_cast<uint2*>(g_zl);
    zh[(size_t)w * 64 + 32 + lane] =
        make_uint2(*reinterpret_cast<unsigned int*>(&hA), *reinterpret_cast<unsigned int*>(&hB));
    zl[(size_t)w * 64 + 32 + lane] =
        make_uint2(*reinterpret_cast<unsigned int*>(&lA), *reinterpret_cast<unsigned int*>(&lB));
}

// Exact fallback for overflowed nodes (c > CAP): full edge rescan, fp32. Never fires in practice.
__global__ void aggregate_fallback_kernel(const float* __restrict__ feat,
                                          const int* __restrict__ src,
                                          const int* __restrict__ dst,
                                          int n_nodes, int n_edges) {
    int w = (blockIdx.x * blockDim.x + threadIdx.x) >> 5;
    if (w >= n_nodes) return;
    int c = g_cnt[w];
    if (c <= CAP) return;
    int lane = threadIdx.x & 31;
    float acc0 = 0.f, acc1 = 0.f, acc2 = 0.f, acc3 = 0.f;
    const float4* f4 = reinterpret_cast<const float4*>(feat);
    for (int e = 0; e < n_edges; e++) {
        if (dst[e] == w) {
            float4 v = f4[(size_t)src[e] * D4 + lane];
            acc0 += v.x; acc1 += v.y; acc2 += v.z; acc3 += v.w;
        }
    }
    float inv = 1.0f / (float)c;
    float m0 = acc0 * inv, m1 = acc1 * inv, m2 = acc2 * inv, m3 = acc3 * inv;
    __nv_bfloat16 h0 = __float2bfloat16_rn(m0);
    __nv_bfloat16 h1 = __float2bfloat16_rn(m1);
    __nv_bfloat16 h2 = __float2bfloat16_rn(m2);
    __nv_bfloat16 h3 = __float2bfloat16_rn(m3);
    __nv_bfloat162 hA = __halves2bfloat162(h0, h1);
    __nv_bfloat162 hB = __halves2bfloat162(h2, h3);
    __nv_bfloat162 lA = __floats2bfloat162_rn(m0 - __bfloat162float(h0),
                                              m1 - __bfloat162float(h1));
    __nv_bfloat162 lB = __floats2bfloat162_rn(m2 - __bfloat162float(h2),
                                              m3 - __bfloat162float(h3));
    uint2* zh = reinterpret_cast<uint2*>(g_zh);
    uint2* zl = reinterpret_cast<uint2*>(g_zl);
    zh[(size_t)w * 64 + 32 + lane] =
        make_uint2(*reinterpret_cast<unsigned int*>(&hA), *reinterpret_cast<unsigned int*>(&hB));
    zl[(size_t)w * 64 + 32 + lane] =
        make_uint2(*reinterpret_cast<unsigned int*>(&lA), *reinterpret_cast<unsigned int*>(&lB));
}

// ---------------- kernel: split-bf16 mma.sync GEMM (unchanged from R12) ----------------
__global__ void __launch_bounds__(256, 1)
gemm_kernel(const float* __restrict__ b_self,
            const float* __restrict__ b_neigh,
            float* __restrict__ out,
            int n_nodes) {
    extern __shared__ char sm[];
    const int tid  = threadIdx.x;
    const int lane = tid & 31;
    const int wid  = tid >> 5;
    const int base = blockIdx.x * 128;

    const int wm = (wid & 1) * 64;         // warp row base
    const int wn = (wid >> 1) * 32;        // warp col base
    const int qr = lane >> 2;              // 0..7
    const int qc = lane & 3;               // 0..3

    if (tid < 128)
        *reinterpret_cast<float*>(sm + SM_BIAS + tid * 4) = b_self[tid] + b_neigh[tid];

    float acc[4][4][4];
    #pragma unroll
    for (int mt = 0; mt < 4; mt++)
        #pragma unroll
        for (int nt = 0; nt < 4; nt++)
            #pragma unroll
            for (int r = 0; r < 4; r++) acc[mt][nt][r] = 0.f;

    const uint4* zh4 = reinterpret_cast<const uint4*>(g_zh);
    const uint4* zl4 = reinterpret_cast<const uint4*>(g_zl);
    const uint4* wh4 = reinterpret_cast<const uint4*>(g_wh);
    const uint4* wl4 = reinterpret_cast<const uint4*>(g_wl);

    #pragma unroll 1
    for (int chunk = 0; chunk < 2; chunk++) {
        #pragma unroll
        for (int i = tid; i < 2048; i += 256) {
            int r = i >> 4;
            int c = i & 15;
            int so = r * ROWB + c * 16;
            size_t zi = (size_t)(base + r) * 32 + chunk * 16 + c;
            size_t wi = (size_t)r * 32 + chunk * 16 + c;
            *reinterpret_cast<uint4*>(sm + SM_AH + so) = __ldg(&zh4[zi]);
            *reinterpret_cast<uint4*>(sm + SM_AL + so) = __ldg(&zl4[zi]);
            *reinterpret_cast<uint4*>(sm + SM_BH + so) = __ldg(&wh4[wi]);
            *reinterpret_cast<uint4*>(sm + SM_BL + so) = __ldg(&wl4[wi]);
        }
        __syncthreads();

        #pragma unroll 2
        for (int ks = 0; ks < 8; ks++) {
            int kb = ks * 32 + qc * 4;

            unsigned ah[4][4], al[4][4];
            #pragma unroll
            for (int mt = 0; mt < 4; mt++) {
                int r0 = (wm + mt * 16 + qr) * ROWB;
                int r8 = r0 + 8 * ROWB;
                ah[mt][0] = *reinterpret_cast<const unsigned*>(sm + SM_AH + r0 + kb);
                ah[mt][1] = *reinterpret_cast<const unsigned*>(sm + SM_AH + r8 + kb);
                ah[mt][2] = *reinterpret_cast<const unsigned*>(sm + SM_AH + r0 + kb + 16);
                ah[mt][3] = *reinterpret_cast<const unsigned*>(sm + SM_AH + r8 + kb + 16);
                al[mt][0] = *reinterpret_cast<const unsigned*>(sm + SM_AL + r0 + kb);
                al[mt][1] = *reinterpret_cast<const unsigned*>(sm + SM_AL + r8 + kb);
                al[mt][2] = *reinterpret_cast<const unsigned*>(sm + SM_AL + r0 + kb + 16);
                al[mt][3] = *reinterpret_cast<const unsigned*>(sm + SM_AL + r8 + kb + 16);
            }
            unsigned bh[4][2], bl[4][2];
            #pragma unroll
            for (int nt = 0; nt < 4; nt++) {
                int n0 = (wn + nt * 8 + qr) * ROWB;
                bh[nt][0] = *reinterpret_cast<const unsigned*>(sm + SM_BH + n0 + kb);
                bh[nt][1] = *reinterpret_cast<const unsigned*>(sm + SM_BH + n0 + kb + 16);
                bl[nt][0] = *reinterpret_cast<const unsigned*>(sm + SM_BL + n0 + kb);
                bl[nt][1] = *reinterpret_cast<const unsigned*>(sm + SM_BL + n0 + kb + 16);
            }

            #pragma unroll
            for (int mt = 0; mt < 4; mt++)
                #pragma unroll
                for (int nt = 0; nt < 4; nt++) {
                    mma_bf16(acc[mt][nt], ah[mt], bh[nt]);
                    mma_bf16(acc[mt][nt], al[mt], bh[nt]);
                    mma_bf16(acc[mt][nt], ah[mt], bl[nt]);
                }
        }
        __syncthreads();
    }

    #pragma unroll
    for (int mt = 0; mt < 4; mt++) {
        int m0 = base + wm + mt * 16 + qr;
        #pragma unroll
        for (int nt = 0; nt < 4; nt++) {
            int n0 = wn + nt * 8 + 2 * qc;
            float2 bv = *reinterpret_cast<const float2*>(sm + SM_BIAS + n0 * 4);
            if (m0 < n_nodes)
                *reinterpret_cast<float2*>(out + (size_t)m0 * D + n0) =
                    make_float2(acc[mt][nt][0] + bv.x, acc[mt][nt][1] + bv.y);
            if (m0 + 8 < n_nodes)
                *reinterpret_cast<float2*>(out + (size_t)(m0 + 8) * D + n0) =
                    make_float2(acc[mt][nt][2] + bv.x, acc[mt][nt][3] + bv.y);
        }
    }
}

// ---------------- launch ----------------
extern "C" void kernel_launch(void* const* d_in, const int* in_sizes, int n_in,
                              void* d_out, int out_size) {
    const float* feat    = (const float*)d_in[0];
    const int*   src     = (const int*)  d_in[1];
    const int*   dst     = (const int*)  d_in[2];
    const float* W_self  = (const float*)d_in[3];
    const float* b_self  = (const float*)d_in[4];
    const float* W_neigh = (const float*)d_in[5];
    const float* b_neigh = (const float*)d_in[6];
    float* out = (float*)d_out;

    const int n_nodes = in_sizes[0] / D;
    const int n_edges = in_sizes[1];

    zero_kernel<<<(MAX_NODES + 255) / 256, 256>>>();
    convert_kernel<<<(MAX_NODES * 64 + 255) / 256, 256>>>(feat, n_nodes * 64);
    prepw_kernel<<<(D * K_TOT + 255) / 256, 256>>>(W_self, W_neigh);

    {
        int n_thr = (n_edges + 7) / 8;
        fill_kernel<<<(n_thr + 255) / 256, 256>>>(src, dst, n_edges);
    }

    {
        int blocks = (MAX_NODES + 7) / 8;           // 8 warps/block
        aggregate_kernel<<<blocks, 256>>>(n_nodes);
        aggregate_fallback_kernel<<<(n_nodes + 7) / 8, 256>>>(feat, src, dst, n_nodes, n_edges);
    }

    {
        cudaFuncSetAttribute(gemm_kernel,
                             cudaFuncAttributeMaxDynamicSharedMemorySize, SM_TOTAL);
        int blocks = MAX_NODES / 128;               // 391
        gemm_kernel<<<blocks, 256, SM_TOTAL>>>(b_self, b_neigh, out, n_nodes);
    }
}

// round 14
// speedup vs baseline: 1.0411x; 1.0411x over previous
#include <cuda_runtime.h>
#include <cuda_bf16.h>
#include <cstdint>

// Problem constants: N=50000 nodes, E=1.6M edges, D_in=D_out=128.
#define D 128
#define D4 (D / 4)
#define MAX_NODES 50048          // 391 * 128
#define CAP 128                  // bucket capacity (Poisson(32); overflow astronomically rare)
#define K_TOT 256                // concat [feat ; mean_neigh]

// GEMM smem: 4 tiles [128 rows][144 B] (64 bf16 payload + 16B pad) + bias
#define ROWB      144
#define TILE_B    (128 * ROWB)   // 18432
#define SM_AH     0
#define SM_AL     (SM_AH + TILE_B)
#define SM_BH     (SM_AL + TILE_B)
#define SM_BL     (SM_BH + TILE_B)
#define SM_BIAS   (SM_BL + TILE_B)
#define SM_TOTAL  (SM_BIAS + 512)          // 74240 B -> 2+ CTAs/SM

// ---------------- scratch (device globals; no allocation allowed) ----------------
__device__ __nv_bfloat16  g_zh[MAX_NODES * K_TOT];  // Z hi  [node][k] (k<128 feat, k>=128 mean)
__device__ __nv_bfloat16  g_zl[MAX_NODES * K_TOT];  // Z lo residual
__device__ __nv_bfloat16  g_wh[D * K_TOT];          // Wcat hi [o][k]
__device__ __nv_bfloat16  g_wl[D * K_TOT];          // Wcat lo residual
__device__ int            g_cnt[MAX_NODES];
__device__ unsigned short g_bucket[MAX_NODES * CAP]; // src ids fit u16 (N=50000 < 65536)

// ---------------- helpers ----------------
__device__ __forceinline__ void mma_bf16(float* d, const unsigned* a, const unsigned* b) {
    asm volatile(
        "mma.sync.aligned.m16n8k16.row.col.f32.bf16.bf16.f32 "
        "{%0,%1,%2,%3}, {%4,%5,%6,%7}, {%8,%9}, {%0,%1,%2,%3};"
        : "+f"(d[0]), "+f"(d[1]), "+f"(d[2]), "+f"(d[3])
        : "r"(a[0]), "r"(a[1]), "r"(a[2]), "r"(a[3]), "r"(b[0]), "r"(b[1]));
}
__device__ __forceinline__ void addf32x2(unsigned long long& acc, unsigned long long a) {
    asm("add.rn.f32x2 %0, %0, %1;" : "+l"(acc) : "l"(a));
}
__device__ __forceinline__ void unpack2(unsigned long long v, float& lo, float& hi) {
    asm("mov.b64 {%0, %1}, %2;" : "=f"(lo), "=f"(hi) : "l"(v));
}
__device__ __forceinline__ unsigned long long bf2_to_f32x2(unsigned int v) {
    unsigned long long r;
    asm("{\n\t"
        ".reg .b32 lo, hi;\n\t"
        "shl.b32 lo, %1, 16;\n\t"
        "and.b32 hi, %1, 0xFFFF0000;\n\t"
        "mov.b64 %0, {lo, hi};\n\t"
        "}" : "=l"(r) : "r"(v));
    return r;
}

// ---------------- kernel: merged prep (zero counters + feat hi/lo + weight hi/lo) ----------------
__global__ void prep_kernel(const float* __restrict__ feat,
                            const float* __restrict__ W_self,
                            const float* __restrict__ W_neigh,
                            int n_f2) {
    int i = blockIdx.x * blockDim.x + threadIdx.x;

    // convert feat -> (zh, zl) first half; pad rows zeroed  [MAX_NODES*64 float2 units]
    if (i < MAX_NODES * 64) {
        int node = i >> 6;
        int c2   = i & 63;
        __nv_bfloat162* zh2 = reinterpret_cast<__nv_bfloat162*>(g_zh);
        __nv_bfloat162* zl2 = reinterpret_cast<__nv_bfloat162*>(g_zl);
        int idx = node * 128 + c2;
        if (i < n_f2) {
            float2 f = reinterpret_cast<const float2*>(feat)[i];
            __nv_bfloat16 hx = __float2bfloat16_rn(f.x);
            __nv_bfloat16 hy = __float2bfloat16_rn(f.y);
            zh2[idx] = __halves2bfloat162(hx, hy);
            zl2[idx] = __floats2bfloat162_rn(f.x - __bfloat162float(hx),
                                             f.y - __bfloat162float(hy));
        } else {
            __nv_bfloat162 z = __floats2bfloat162_rn(0.f, 0.f);
            zh2[idx] = z; zl2[idx] = z;
        }
    }
    // zero in-degree counters
    if (i < MAX_NODES) g_cnt[i] = 0;
    // weight hi/lo split, [o][k] concat layout
    if (i < D * K_TOT) {
        int o = i >> 8;
        int k = i & 255;
        float w = (k < D) ? W_self[o * D + k] : W_neigh[o * D + (k - D)];
        __nv_bfloat16 h = __float2bfloat16_rn(w);
        g_wh[i] = h;
        g_wl[i] = __float2bfloat16_rn(w - __bfloat162float(h));
    }
}

// ---------------- kernel: fill per-dst buckets (lane-interleaved, 8 edges/thread) ----------------
// Warp w covers edges [w*256, w*256+256); thread handles e = base + lane + 32*j -> all
// loads warp-coalesced (128B per LDG wavefront), 8 independent atomic->store chains.
__global__ void fill_kernel(const int* __restrict__ src,
                            const int* __restrict__ dst,
                            int n_edges) {
    int g = blockIdx.x * blockDim.x + threadIdx.x;
    int warp = g >> 5;
    int lane = g & 31;
    int e0 = warp * 256 + lane;

    int s[8], d[8];
    bool v[8];
    #pragma unroll
    for (int j = 0; j < 8; j++) {
        int e = e0 + 32 * j;
        v[j] = (e < n_edges);
        s[j] = v[j] ? src[e] : 0;
        d[j] = v[j] ? dst[e] : 0;
    }
    int p[8];
    #pragma unroll
    for (int j = 0; j < 8; j++)
        p[j] = v[j] ? atomicAdd(&g_cnt[d[j]], 1) : CAP;
    #pragma unroll
    for (int j = 0; j < 8; j++)
        if (v[j] && p[j] < CAP)
            g_bucket[d[j] * CAP + p[j]] = (unsigned short)s[j];
    // pos >= CAP handled by exact rescan path inside aggregate_kernel (never in practice)
}

// ---------------- kernel: warp-per-node pull aggregation (inlined exact fallback) ----------------
__global__ void aggregate_kernel(const float* __restrict__ feat,
                                 const int* __restrict__ src,
                                 const int* __restrict__ dst,
                                 int n_nodes, int n_edges) {
    int w = (blockIdx.x * blockDim.x + threadIdx.x) >> 5;
    if (w >= MAX_NODES) return;
    int lane = threadIdx.x & 31;

    int c = g_cnt[w];                       // 0 for pad rows
    float m0, m1, m2, m3;

    if (c <= CAP) {
        // fast path: bucketed bf16 gather, exact packed-f32x2 accumulate
        unsigned long long acc01 = 0ull, acc23 = 0ull;
        const uint2* fb = reinterpret_cast<const uint2*>(g_zh);  // row = 64 uint2; feat half first 32
        const unsigned short* bk = &g_bucket[w * CAP];
        for (int i0 = 0; i0 < c; i0 += 32) {
            int take = min(32, c - i0);
            int my = (lane < take) ? (int)bk[i0 + lane] : 0;
            #pragma unroll 4
            for (int j = 0; j < take; j++) {
                int s = __shfl_sync(0xffffffffu, my, j);
                uint2 vv = __ldg(&fb[(size_t)s * 64 + lane]);    // 4 bf16 cols at 4*lane
                addf32x2(acc01, bf2_to_f32x2(vv.x));
                addf32x2(acc23, bf2_to_f32x2(vv.y));
            }
        }
        float inv = 1.0f / fmaxf((float)c, 1.0f);
        unpack2(acc01, m0, m1);
        unpack2(acc23, m2, m3);
        m0 *= inv; m1 *= inv; m2 *= inv; m3 *= inv;
    } else {
        // exact fallback (statistically never): full edge rescan, fp32 gather
        float a0 = 0.f, a1 = 0.f, a2 = 0.f, a3 = 0.f;
        const float4* f4 = reinterpret_cast<const float4*>(feat);
        for (int e = 0; e < n_edges; e++) {
            if (dst[e] == w) {
                float4 vv = f4[(size_t)src[e] * D4 + lane];
                a0 += vv.x; a1 += vv.y; a2 += vv.z; a3 += vv.w;
            }
        }
        float inv = 1.0f / (float)c;
        m0 = a0 * inv; m1 = a1 * inv; m2 = a2 * inv; m3 = a3 * inv;
    }

    // split mean into hi/lo bf16 and store into Z second half
    __nv_bfloat16 h0 = __float2bfloat16_rn(m0);
    __nv_bfloat16 h1 = __float2bfloat16_rn(m1);
    __nv_bfloat16 h2 = __float2bfloat16_rn(m2);
    __nv_bfloat16 h3 = __float2bfloat16_rn(m3);
    __nv_bfloat162 hA = __halves2bfloat162(h0, h1);
    __nv_bfloat162 hB = __halves2bfloat162(h2, h3);
    __nv_bfloat162 lA = __floats2bfloat162_rn(m0 - __bfloat162float(h0),
                                              m1 - __bfloat162float(h1));
    __nv_bfloat162 lB = __floats2bfloat162_rn(m2 - __bfloat162float(h2),
                                              m3 - __bfloat162float(h3));
    uint2* zh = reinterpret_cast<uint2*>(g_zh);
    uint2* zl = reinterpret_cast<uint2*>(g_zl);
    zh[(size_t)w * 64 + 32 + lane] =
        make_uint2(*reinterpret_cast<unsigned int*>(&hA), *reinterpret_cast<unsigned int*>(&hB));
    zl[(size_t)w * 64 + 32 + lane] =
        make_uint2(*reinterpret_cast<unsigned int*>(&lA), *reinterpret_cast<unsigned int*>(&lB));
}

// ---------------- kernel: split-bf16 mma.sync GEMM (K-chunk 64 -> 2+ CTAs/SM) ----------------
// Per CTA: 128 rows x 128 cols; K=256 in 4 chunks of 64.
// acc += Zh*Wh + Zl*Wh + Zh*Wl  (3 mma passes, shared fragments).
// 8 warps: warp tile 64 rows x 32 cols = 4 m-tiles x 4 n-tiles of m16n8k16.
__global__ void __launch_bounds__(256, 2)
gemm_kernel(const float* __restrict__ b_self,
            const float* __restrict__ b_neigh,
            float* __restrict__ out,
            int n_nodes) {
    extern __shared__ char sm[];
    const int tid  = threadIdx.x;
    const int lane = tid & 31;
    const int wid  = tid >> 5;
    const int base = blockIdx.x * 128;

    const int wm = (wid & 1) * 64;         // warp row base
    const int wn = (wid >> 1) * 32;        // warp col base
    const int qr = lane >> 2;              // 0..7
    const int qc = lane & 3;               // 0..3

    if (tid < 128)
        *reinterpret_cast<float*>(sm + SM_BIAS + tid * 4) = b_self[tid] + b_neigh[tid];

    float acc[4][4][4];
    #pragma unroll
    for (int mt = 0; mt < 4; mt++)
        #pragma unroll
        for (int nt = 0; nt < 4; nt++)
            #pragma unroll
            for (int r = 0; r < 4; r++) acc[mt][nt][r] = 0.f;

    const uint4* zh4 = reinterpret_cast<const uint4*>(g_zh);
    const uint4* zl4 = reinterpret_cast<const uint4*>(g_zl);
    const uint4* wh4 = reinterpret_cast<const uint4*>(g_wh);
    const uint4* wl4 = reinterpret_cast<const uint4*>(g_wl);

    #pragma unroll 1
    for (int chunk = 0; chunk < 4; chunk++) {
        // --- stage 4 tiles (row = 8 uint4 = 64 bf16 of this k-chunk) ---
        #pragma unroll
        for (int i = tid; i < 1024; i += 256) {
            int r = i >> 3;
            int c = i & 7;
            int so = r * ROWB + c * 16;
            size_t zi = (size_t)(base + r) * 32 + chunk * 8 + c;
            size_t wi = (size_t)r * 32 + chunk * 8 + c;
            *reinterpret_cast<uint4*>(sm + SM_AH + so) = __ldg(&zh4[zi]);
            *reinterpret_cast<uint4*>(sm + SM_AL + so) = __ldg(&zl4[zi]);
            *reinterpret_cast<uint4*>(sm + SM_BH + so) = __ldg(&wh4[wi]);
            *reinterpret_cast<uint4*>(sm + SM_BL + so) = __ldg(&wl4[wi]);
        }
        __syncthreads();

        // --- 4 k-steps of 16 ---
        #pragma unroll
        for (int ks = 0; ks < 4; ks++) {
            int kb = ks * 32 + qc * 4;

            unsigned ah[4][4], al[4][4];
            #pragma unroll
            for (int mt = 0; mt < 4; mt++) {
                int r0 = (wm + mt * 16 + qr) * ROWB;
                int r8 = r0 + 8 * ROWB;
                ah[mt][0] = *reinterpret_cast<const unsigned*>(sm + SM_AH + r0 + kb);
                ah[mt][1] = *reinterpret_cast<const unsigned*>(sm + SM_AH + r8 + kb);
                ah[mt][2] = *reinterpret_cast<const unsigned*>(sm + SM_AH + r0 + kb + 16);
                ah[mt][3] = *reinterpret_cast<const unsigned*>(sm + SM_AH + r8 + kb + 16);
                al[mt][0] = *reinterpret_cast<const unsigned*>(sm + SM_AL + r0 + kb);
                al[mt][1] = *reinterpret_cast<const unsigned*>(sm + SM_AL + r8 + kb);
                al[mt][2] = *reinterpret_cast<const unsigned*>(sm + SM_AL + r0 + kb + 16);
                al[mt][3] = *reinterpret_cast<const unsigned*>(sm + SM_AL + r8 + kb + 16);
            }
            unsigned bh[4][2], bl[4][2];
            #pragma unroll
            for (int nt = 0; nt < 4; nt++) {
                int n0 = (wn + nt * 8 + qr) * ROWB;
                bh[nt][0] = *reinterpret_cast<const unsigned*>(sm + SM_BH + n0 + kb);
                bh[nt][1] = *reinterpret_cast<const unsigned*>(sm + SM_BH + n0 + kb + 16);
                bl[nt][0] = *reinterpret_cast<const unsigned*>(sm + SM_BL + n0 + kb);
                bl[nt][1] = *reinterpret_cast<const unsigned*>(sm + SM_BL + n0 + kb + 16);
            }

            #pragma unroll
            for (int mt = 0; mt < 4; mt++)
                #pragma unroll
                for (int nt = 0; nt < 4; nt++) {
                    mma_bf16(acc[mt][nt], ah[mt], bh[nt]);
                    mma_bf16(acc[mt][nt], al[mt], bh[nt]);
                    mma_bf16(acc[mt][nt], ah[mt], bl[nt]);
                }
        }
        __syncthreads();
    }

    // --- epilogue: bias + direct float2 stores ---
    #pragma unroll
    for (int mt = 0; mt < 4; mt++) {
        int m0 = base + wm + mt * 16 + qr;
        #pragma unroll
        for (int nt = 0; nt < 4; nt++) {
            int n0 = wn + nt * 8 + 2 * qc;
            float2 bv = *reinterpret_cast<const float2*>(sm + SM_BIAS + n0 * 4);
            if (m0 < n_nodes)
                *reinterpret_cast<float2*>(out + (size_t)m0 * D + n0) =
                    make_float2(acc[mt][nt][0] + bv.x, acc[mt][nt][1] + bv.y);
            if (m0 + 8 < n_nodes)
                *reinterpret_cast<float2*>(out + (size_t)(m0 + 8) * D + n0) =
                    make_float2(acc[mt][nt][2] + bv.x, acc[mt][nt][3] + bv.y);
        }
    }
}

// ---------------- launch ----------------
extern "C" void kernel_launch(void* const* d_in, const int* in_sizes, int n_in,
                              void* d_out, int out_size) {
    const float* feat    = (const float*)d_in[0];
    const int*   src     = (const int*)  d_in[1];
    const int*   dst     = (const int*)  d_in[2];
    const float* W_self  = (const float*)d_in[3];
    const float* b_self  = (const float*)d_in[4];
    const float* W_neigh = (const float*)d_in[5];
    const float* b_neigh = (const float*)d_in[6];
    float* out = (float*)d_out;

    const int n_nodes = in_sizes[0] / D;
    const int n_edges = in_sizes[1];

    // merged prep: zero counters + feat hi/lo convert + weight hi/lo split
    prep_kernel<<<(MAX_NODES * 64 + 255) / 256, 256>>>(feat, W_self, W_neigh, n_nodes * 64);

    // bucket fill: lane-interleaved, 8 edges/thread
    {
        int warps = (n_edges + 255) / 256;
        int blocks = (warps * 32 + 255) / 256;
        fill_kernel<<<blocks, 256>>>(src, dst, n_edges);
    }

    // pull aggregation (exact fallback inlined) -> Z second half = mean hi/lo
    {
        int blocks = (MAX_NODES + 7) / 8;           // 8 warps/block
        aggregate_kernel<<<blocks, 256>>>(feat, src, dst, n_nodes, n_edges);
    }

    // split-bf16 tensor-core GEMM
    {
        cudaFuncSetAttribute(gemm_kernel,
                             cudaFuncAttributeMaxDynamicSharedMemorySize, SM_TOTAL);
        int blocks = MAX_NODES / 128;               // 391
        gemm_kernel<<<blocks, 256, SM_TOTAL>>>(b_self, b_neigh, out, n_nodes);
    }
}

// round 16
// speedup vs baseline: 1.0504x; 1.0089x over previous
#include <cuda_runtime.h>
#include <cuda_bf16.h>
#include <cstdint>

// Problem constants: N=50000 nodes, E=1.6M edges, D_in=D_out=128.
#define D 128
#define D4 (D / 4)
#define MAX_NODES 50048          // 391 * 128
#define CAP 128                  // bucket capacity (Poisson(32); overflow astronomically rare)
#define K_TOT 256                // concat [feat ; mean_neigh]

// GEMM smem: DOUBLE-buffered 4 tiles [128 rows][144 B] + bias
#define ROWB      144            // 64 bf16 payload + 16B pad (conflict-free fragment banks)
#define TILE_B    (128 * ROWB)   // 18432
#define BUF_B     (4 * TILE_B)   // 73728 per stage buffer
#define SM_AH     0
#define SM_AL     (1 * TILE_B)
#define SM_BH     (2 * TILE_B)
#define SM_BL     (3 * TILE_B)
#define SM_BIAS   (2 * BUF_B)
#define SM_TOTAL  (SM_BIAS + 512)          // 147968 B -> 1 CTA/SM

// ---------------- scratch (device globals; no allocation allowed) ----------------
__device__ __nv_bfloat16  g_zh[MAX_NODES * K_TOT];  // Z hi  [node][k] (k<128 feat, k>=128 mean)
__device__ __nv_bfloat16  g_zl[MAX_NODES * K_TOT];  // Z lo residual
__device__ __nv_bfloat16  g_wh[D * K_TOT];          // Wcat hi [o][k]
__device__ __nv_bfloat16  g_wl[D * K_TOT];          // Wcat lo residual
__device__ int            g_cnt[MAX_NODES];
__device__ unsigned short g_bucket[MAX_NODES * CAP]; // src ids fit u16 (N=50000 < 65536)

// ---------------- helpers ----------------
__device__ __forceinline__ void mma_bf16(float* d, const unsigned* a, const unsigned* b) {
    asm volatile(
        "mma.sync.aligned.m16n8k16.row.col.f32.bf16.bf16.f32 "
        "{%0,%1,%2,%3}, {%4,%5,%6,%7}, {%8,%9}, {%0,%1,%2,%3};"
        : "+f"(d[0]), "+f"(d[1]), "+f"(d[2]), "+f"(d[3])
        : "r"(a[0]), "r"(a[1]), "r"(a[2]), "r"(a[3]), "r"(b[0]), "r"(b[1]));
}
__device__ __forceinline__ void addf32x2(unsigned long long& acc, unsigned long long a) {
    asm("add.rn.f32x2 %0, %0, %1;" : "+l"(acc) : "l"(a));
}
__device__ __forceinline__ void unpack2(unsigned long long v, float& lo, float& hi) {
    asm("mov.b64 {%0, %1}, %2;" : "=f"(lo), "=f"(hi) : "l"(v));
}
__device__ __forceinline__ unsigned long long bf2_to_f32x2(unsigned int v) {
    unsigned long long r;
    asm("{\n\t"
        ".reg .b32 lo, hi;\n\t"
        "shl.b32 lo, %1, 16;\n\t"
        "and.b32 hi, %1, 0xFFFF0000;\n\t"
        "mov.b64 %0, {lo, hi};\n\t"
        "}" : "=l"(r) : "r"(v));
    return r;
}
__device__ __forceinline__ uint32_t smem_u32(const void* p) {
    uint32_t a;
    asm("{ .reg .u64 t; cvta.to.shared.u64 t, %1; cvt.u32.u64 %0, t; }" : "=r"(a) : "l"(p));
    return a;
}
__device__ __forceinline__ void cp16(uint32_t s, const void* g) {
    asm volatile("cp.async.cg.shared.global [%0], [%1], 16;" :: "r"(s), "l"(g) : "memory");
}
#define CP_COMMIT()  asm volatile("cp.async.commit_group;" ::: "memory")
#define CP_WAIT(n)   asm volatile("cp.async.wait_group %0;" :: "n"(n) : "memory")

// ---------------- kernel: merged prep (zero counters + feat hi/lo + weight hi/lo) ----------------
__global__ void prep_kernel(const float* __restrict__ feat,
                            const float* __restrict__ W_self,
                            const float* __restrict__ W_neigh,
                            int n_f2) {
    int i = blockIdx.x * blockDim.x + threadIdx.x;

    if (i < MAX_NODES * 64) {
        int node = i >> 6;
        int c2   = i & 63;
        __nv_bfloat162* zh2 = reinterpret_cast<__nv_bfloat162*>(g_zh);
        __nv_bfloat162* zl2 = reinterpret_cast<__nv_bfloat162*>(g_zl);
        int idx = node * 128 + c2;
        if (i < n_f2) {
            float2 f = reinterpret_cast<const float2*>(feat)[i];
            __nv_bfloat16 hx = __float2bfloat16_rn(f.x);
            __nv_bfloat16 hy = __float2bfloat16_rn(f.y);
            zh2[idx] = __halves2bfloat162(hx, hy);
            zl2[idx] = __floats2bfloat162_rn(f.x - __bfloat162float(hx),
                                             f.y - __bfloat162float(hy));
        } else {
            __nv_bfloat162 z = __floats2bfloat162_rn(0.f, 0.f);
            zh2[idx] = z; zl2[idx] = z;
        }
    }
    if (i < MAX_NODES) g_cnt[i] = 0;
    if (i < D * K_TOT) {
        int o = i >> 8;
        int k = i & 255;
        float w = (k < D) ? W_self[o * D + k] : W_neigh[o * D + (k - D)];
        __nv_bfloat16 h = __float2bfloat16_rn(w);
        g_wh[i] = h;
        g_wl[i] = __float2bfloat16_rn(w - __bfloat162float(h));
    }
}

// ---------------- kernel: fill per-dst buckets (lane-interleaved, 8 edges/thread) ----------------
__global__ void fill_kernel(const int* __restrict__ src,
                            const int* __restrict__ dst,
                            int n_edges) {
    int g = blockIdx.x * blockDim.x + threadIdx.x;
    int warp = g >> 5;
    int lane = g & 31;
    int e0 = warp * 256 + lane;

    int s[8], d[8];
    bool v[8];
    #pragma unroll
    for (int j = 0; j < 8; j++) {
        int e = e0 + 32 * j;
        v[j] = (e < n_edges);
        s[j] = v[j] ? src[e] : 0;
        d[j] = v[j] ? dst[e] : 0;
    }
    int p[8];
    #pragma unroll
    for (int j = 0; j < 8; j++)
        p[j] = v[j] ? atomicAdd(&g_cnt[d[j]], 1) : CAP;
    #pragma unroll
    for (int j = 0; j < 8; j++)
        if (v[j] && p[j] < CAP)
            g_bucket[d[j] * CAP + p[j]] = (unsigned short)s[j];
}

// ---------------- kernel: warp-per-node pull aggregation (inlined exact fallback) ----------------
__global__ void aggregate_kernel(const float* __restrict__ feat,
                                 const int* __restrict__ src,
                                 const int* __restrict__ dst,
                                 int n_nodes, int n_edges) {
    int w = (blockIdx.x * blockDim.x + threadIdx.x) >> 5;
    if (w >= MAX_NODES) return;
    int lane = threadIdx.x & 31;

    int c = g_cnt[w];
    float m0, m1, m2, m3;

    if (c <= CAP) {
        unsigned long long acc01 = 0ull, acc23 = 0ull;
        const uint2* fb = reinterpret_cast<const uint2*>(g_zh);
        const unsigned short* bk = &g_bucket[w * CAP];
        for (int i0 = 0; i0 < c; i0 += 32) {
            int take = min(32, c - i0);
            int my = (lane < take) ? (int)bk[i0 + lane] : 0;
            #pragma unroll 4
            for (int j = 0; j < take; j++) {
                int s = __shfl_sync(0xffffffffu, my, j);
                uint2 vv = __ldg(&fb[(size_t)s * 64 + lane]);
                addf32x2(acc01, bf2_to_f32x2(vv.x));
                addf32x2(acc23, bf2_to_f32x2(vv.y));
            }
        }
        float inv = 1.0f / fmaxf((float)c, 1.0f);
        unpack2(acc01, m0, m1);
        unpack2(acc23, m2, m3);
        m0 *= inv; m1 *= inv; m2 *= inv; m3 *= inv;
    } else {
        float a0 = 0.f, a1 = 0.f, a2 = 0.f, a3 = 0.f;
        const float4* f4 = reinterpret_cast<const float4*>(feat);
        for (int e = 0; e < n_edges; e++) {
            if (dst[e] == w) {
                float4 vv = f4[(size_t)src[e] * D4 + lane];
                a0 += vv.x; a1 += vv.y; a2 += vv.z; a3 += vv.w;
            }
        }
        float inv = 1.0f / (float)c;
        m0 = a0 * inv; m1 = a1 * inv; m2 = a2 * inv; m3 = a3 * inv;
    }

    __nv_bfloat16 h0 = __float2bfloat16_rn(m0);
    __nv_bfloat16 h1 = __float2bfloat16_rn(m1);
    __nv_bfloat16 h2 = __float2bfloat16_rn(m2);
    __nv_bfloat16 h3 = __float2bfloat16_rn(m3);
    __nv_bfloat162 hA = __halves2bfloat162(h0, h1);
    __nv_bfloat162 hB = __halves2bfloat162(h2, h3);
    __nv_bfloat162 lA = __floats2bfloat162_rn(m0 - __bfloat162float(h0),
                                              m1 - __bfloat162float(h1));
    __nv_bfloat162 lB = __floats2bfloat162_rn(m2 - __bfloat162float(h2),
                                              m3 - __bfloat162float(h3));
    uint2* zh = reinterpret_cast<uint2*>(g_zh);
    uint2* zl = reinterpret_cast<uint2*>(g_zl);
    zh[(size_t)w * 64 + 32 + lane] =
        make_uint2(*reinterpret_cast<unsigned int*>(&hA), *reinterpret_cast<unsigned int*>(&hB));
    zl[(size_t)w * 64 + 32 + lane] =
        make_uint2(*reinterpret_cast<unsigned int*>(&lA), *reinterpret_cast<unsigned int*>(&lB));
}

// ---------------- kernel: split-bf16 mma.sync GEMM, cp.async double-buffer pipeline ----------------
// Per CTA: 128 rows x 128 cols; K=256 in 4 chunks of 64; prefetch chunk c+1 during compute of c.
// acc += Zh*Wh + Zl*Wh + Zh*Wl. 8 warps: warp tile 64x32 = 4 m-tiles x 4 n-tiles of m16n8k16.
__global__ void __launch_bounds__(256, 1)
gemm_kernel(const float* __restrict__ b_self,
            const float* __restrict__ b_neigh,
            float* __restrict__ out,
            int n_nodes) {
    extern __shared__ char sm[];
    const uint32_t smb = smem_u32(sm);
    const int tid  = threadIdx.x;
    const int lane = tid & 31;
    const int wid  = tid >> 5;
    const int base = blockIdx.x * 128;

    const int wm = (wid & 1) * 64;
    const int wn = (wid >> 1) * 32;
    const int qr = lane >> 2;
    const int qc = lane & 3;

    if (tid < 128)
        *reinterpret_cast<float*>(sm + SM_BIAS + tid * 4) = b_self[tid] + b_neigh[tid];

    const uint4* zh4 = reinterpret_cast<const uint4*>(g_zh);
    const uint4* zl4 = reinterpret_cast<const uint4*>(g_zl);
    const uint4* wh4 = reinterpret_cast<const uint4*>(g_wh);
    const uint4* wl4 = reinterpret_cast<const uint4*>(g_wl);

    // stage one k-chunk (64 wide) into buffer `buf` via cp.async
    auto stage = [&](int chunk, int buf) {
        uint32_t sb = smb + buf * BUF_B;
        #pragma unroll
        for (int i = tid; i < 1024; i += 256) {
            int r = i >> 3;
            int c = i & 7;
            uint32_t so = r * ROWB + c * 16;
            size_t zi = (size_t)(base + r) * 32 + chunk * 8 + c;
            size_t wi = (size_t)r * 32 + chunk * 8 + c;
            cp16(sb + SM_AH + so, zh4 + zi);
            cp16(sb + SM_AL + so, zl4 + zi);
            cp16(sb + SM_BH + so, wh4 + wi);
            cp16(sb + SM_BL + so, wl4 + wi);
        }
    };

    float acc[4][4][4];
    #pragma unroll
    for (int mt = 0; mt < 4; mt++)
        #pragma unroll
        for (int nt = 0; nt < 4; nt++)
            #pragma unroll
            for (int r = 0; r < 4; r++) acc[mt][nt][r] = 0.f;

    stage(0, 0);
    CP_COMMIT();

    #pragma unroll 1
    for (int chunk = 0; chunk < 4; chunk++) {
        if (chunk + 1 < 4) {
            stage(chunk + 1, (chunk + 1) & 1);
            CP_COMMIT();
            CP_WAIT(1);                    // chunk's group complete; prefetch may run
        } else {
            CP_WAIT(0);
        }
        __syncthreads();

        const char* sb = sm + (chunk & 1) * BUF_B;

        #pragma unroll
        for (int ks = 0; ks < 4; ks++) {
            int kb = ks * 32 + qc * 4;

            unsigned ah[4][4], al[4][4];
            #pragma unroll
            for (int mt = 0; mt < 4; mt++) {
                int r0 = (wm + mt * 16 + qr) * ROWB;
                int r8 = r0 + 8 * ROWB;
                ah[mt][0] = *reinterpret_cast<const unsigned*>(sb + SM_AH + r0 + kb);
                ah[mt][1] = *reinterpret_cast<const unsigned*>(sb + SM_AH + r8 + kb);
                ah[mt][2] = *reinterpret_cast<const unsigned*>(sb + SM_AH + r0 + kb + 16);
                ah[mt][3] = *reinterpret_cast<const unsigned*>(sb + SM_AH + r8 + kb + 16);
                al[mt][0] = *reinterpret_cast<const unsigned*>(sb + SM_AL + r0 + kb);
                al[mt][1] = *reinterpret_cast<const unsigned*>(sb + SM_AL + r8 + kb);
                al[mt][2] = *reinterpret_cast<const unsigned*>(sb + SM_AL + r0 + kb + 16);
                al[mt][3] = *reinterpret_cast<const unsigned*>(sb + SM_AL + r8 + kb + 16);
            }
            unsigned bh[4][2], bl[4][2];
            #pragma unroll
            for (int nt = 0; nt < 4; nt++) {
                int n0 = (wn + nt * 8 + qr) * ROWB;
                bh[nt][0] = *reinterpret_cast<const unsigned*>(sb + SM_BH + n0 + kb);
                bh[nt][1] = *reinterpret_cast<const unsigned*>(sb + SM_BH + n0 + kb + 16);
                bl[nt][0] = *reinterpret_cast<const unsigned*>(sb + SM_BL + n0 + kb);
                bl[nt][1] = *reinterpret_cast<const unsigned*>(sb + SM_BL + n0 + kb + 16);
            }

            #pragma unroll
            for (int mt = 0; mt < 4; mt++)
                #pragma unroll
                for (int nt = 0; nt < 4; nt++) {
                    mma_bf16(acc[mt][nt], ah[mt], bh[nt]);
                    mma_bf16(acc[mt][nt], al[mt], bh[nt]);
                    mma_bf16(acc[mt][nt], ah[mt], bl[nt]);
                }
        }
        __syncthreads();   // seal reads of this buffer before it is restaged
    }

    // --- epilogue: bias + direct float2 stores ---
    #pragma unroll
    for (int mt = 0; mt < 4; mt++) {
        int m0 = base + wm + mt * 16 + qr;
        #pragma unroll
        for (int nt = 0; nt < 4; nt++) {
            int n0 = wn + nt * 8 + 2 * qc;
            float2 bv = *reinterpret_cast<const float2*>(sm + SM_BIAS + n0 * 4);
            if (m0 < n_nodes)
                *reinterpret_cast<float2*>(out + (size_t)m0 * D + n0) =
                    make_float2(acc[mt][nt][0] + bv.x, acc[mt][nt][1] + bv.y);
            if (m0 + 8 < n_nodes)
                *reinterpret_cast<float2*>(out + (size_t)(m0 + 8) * D + n0) =
                    make_float2(acc[mt][nt][2] + bv.x, acc[mt][nt][3] + bv.y);
        }
    }
}

// ---------------- launch ----------------
extern "C" void kernel_launch(void* const* d_in, const int* in_sizes, int n_in,
                              void* d_out, int out_size) {
    const float* feat    = (const float*)d_in[0];
    const int*   src     = (const int*)  d_in[1];
    const int*   dst     = (const int*)  d_in[2];
    const float* W_self  = (const float*)d_in[3];
    const float* b_self  = (const float*)d_in[4];
    const float* W_neigh = (const float*)d_in[5];
    const float* b_neigh = (const float*)d_in[6];
    float* out = (float*)d_out;

    const int n_nodes = in_sizes[0] / D;
    const int n_edges = in_sizes[1];

    prep_kernel<<<(MAX_NODES * 64 + 255) / 256, 256>>>(feat, W_self, W_neigh, n_nodes * 64);

    {
        int warps = (n_edges + 255) / 256;
        int blocks = (warps * 32 + 255) / 256;
        fill_kernel<<<blocks, 256>>>(src, dst, n_edges);
    }

    {
        int blocks = (MAX_NODES + 7) / 8;
        aggregate_kernel<<<blocks, 256>>>(feat, src, dst, n_nodes, n_edges);
    }

    {
        cudaFuncSetAttribute(gemm_kernel,
                             cudaFuncAttributeMaxDynamicSharedMemorySize, SM_TOTAL);
        int blocks = MAX_NODES / 128;               // 391
        gemm_kernel<<<blocks, 256, SM_TOTAL>>>(b_self, b_neigh, out, n_nodes);
    }
}

// round 17
// speedup vs baseline: 1.0521x; 1.0016x over previous
#include <cuda_runtime.h>
#include <cuda_bf16.h>
#include <cstdint>

// Problem constants: N=50000 nodes, E=1.6M edges, D_in=D_out=128.
#define D 128
#define D4 (D / 4)
#define MAX_NODES 50048          // 391 * 128
#define CAP 128                  // bucket capacity (Poisson(32); overflow astronomically rare)
#define K_TOT 256                // concat [feat ; mean_neigh]

// GEMM smem: DOUBLE-buffered 4 tiles [128 rows][80 B] (32 bf16 + 16B pad) + bias
#define ROWB      80
#define TILE_B    (128 * ROWB)   // 10240
#define BUF_B     (4 * TILE_B)   // 40960 per stage buffer
#define SM_AH     0
#define SM_AL     (1 * TILE_B)
#define SM_BH     (2 * TILE_B)
#define SM_BL     (3 * TILE_B)
#define SM_BIAS   (2 * BUF_B)    // 81920
#define SM_TOTAL  (SM_BIAS + 512)          // 82432 B -> 2 CTAs/SM

// ---------------- scratch (device globals; no allocation allowed) ----------------
__device__ __nv_bfloat16  g_zh[MAX_NODES * K_TOT];  // Z hi  [node][k] (k<128 feat, k>=128 mean)
__device__ __nv_bfloat16  g_zl[MAX_NODES * K_TOT];  // Z lo residual
__device__ __nv_bfloat16  g_wh[D * K_TOT];          // Wcat hi [o][k]
__device__ __nv_bfloat16  g_wl[D * K_TOT];          // Wcat lo residual
__device__ int            g_cnt[MAX_NODES];
__device__ unsigned short g_bucket[MAX_NODES * CAP]; // src ids fit u16 (N=50000 < 65536)

// ---------------- helpers ----------------
__device__ __forceinline__ void mma_bf16(float* d, const unsigned* a, const unsigned* b) {
    asm volatile(
        "mma.sync.aligned.m16n8k16.row.col.f32.bf16.bf16.f32 "
        "{%0,%1,%2,%3}, {%4,%5,%6,%7}, {%8,%9}, {%0,%1,%2,%3};"
        : "+f"(d[0]), "+f"(d[1]), "+f"(d[2]), "+f"(d[3])
        : "r"(a[0]), "r"(a[1]), "r"(a[2]), "r"(a[3]), "r"(b[0]), "r"(b[1]));
}
__device__ __forceinline__ void addf32x2(unsigned long long& acc, unsigned long long a) {
    asm("add.rn.f32x2 %0, %0, %1;" : "+l"(acc) : "l"(a));
}
__device__ __forceinline__ void unpack2(unsigned long long v, float& lo, float& hi) {
    asm("mov.b64 {%0, %1}, %2;" : "=f"(lo), "=f"(hi) : "l"(v));
}
__device__ __forceinline__ unsigned long long bf2_to_f32x2(unsigned int v) {
    unsigned long long r;
    asm("{\n\t"
        ".reg .b32 lo, hi;\n\t"
        "shl.b32 lo, %1, 16;\n\t"
        "and.b32 hi, %1, 0xFFFF0000;\n\t"
        "mov.b64 %0, {lo, hi};\n\t"
        "}" : "=l"(r) : "r"(v));
    return r;
}
__device__ __forceinline__ uint32_t smem_u32(const void* p) {
    uint32_t a;
    asm("{ .reg .u64 t; cvta.to.shared.u64 t, %1; cvt.u32.u64 %0, t; }" : "=r"(a) : "l"(p));
    return a;
}
__device__ __forceinline__ void cp16(uint32_t s, const void* g) {
    asm volatile("cp.async.cg.shared.global [%0], [%1], 16;" :: "r"(s), "l"(g) : "memory");
}
#define CP_COMMIT()  asm volatile("cp.async.commit_group;" ::: "memory")
#define CP_WAIT(n)   asm volatile("cp.async.wait_group %0;" :: "n"(n) : "memory")

// ---------------- kernel: merged prep (zero counters + feat hi/lo + weight hi/lo) ----------------
__global__ void prep_kernel(const float* __restrict__ feat,
                            const float* __restrict__ W_self,
                            const float* __restrict__ W_neigh,
                            int n_f2) {
    int i = blockIdx.x * blockDim.x + threadIdx.x;

    if (i < MAX_NODES * 64) {
        int node = i >> 6;
        int c2   = i & 63;
        __nv_bfloat162* zh2 = reinterpret_cast<__nv_bfloat162*>(g_zh);
        __nv_bfloat162* zl2 = reinterpret_cast<__nv_bfloat162*>(g_zl);
        int idx = node * 128 + c2;
        if (i < n_f2) {
            float2 f = reinterpret_cast<const float2*>(feat)[i];
            __nv_bfloat16 hx = __float2bfloat16_rn(f.x);
            __nv_bfloat16 hy = __float2bfloat16_rn(f.y);
            zh2[idx] = __halves2bfloat162(hx, hy);
            zl2[idx] = __floats2bfloat162_rn(f.x - __bfloat162float(hx),
                                             f.y - __bfloat162float(hy));
        } else {
            __nv_bfloat162 z = __floats2bfloat162_rn(0.f, 0.f);
            zh2[idx] = z; zl2[idx] = z;
        }
    }
    if (i < MAX_NODES) g_cnt[i] = 0;
    if (i < D * K_TOT) {
        int o = i >> 8;
        int k = i & 255;
        float w = (k < D) ? W_self[o * D + k] : W_neigh[o * D + (k - D)];
        __nv_bfloat16 h = __float2bfloat16_rn(w);
        g_wh[i] = h;
        g_wl[i] = __float2bfloat16_rn(w - __bfloat162float(h));
    }
}

// ---------------- kernel: fill per-dst buckets (lane-interleaved, 8 edges/thread) ----------------
__global__ void fill_kernel(const int* __restrict__ src,
                            const int* __restrict__ dst,
                            int n_edges) {
    int g = blockIdx.x * blockDim.x + threadIdx.x;
    int warp = g >> 5;
    int lane = g & 31;
    int e0 = warp * 256 + lane;

    int s[8], d[8];
    bool v[8];
    #pragma unroll
    for (int j = 0; j < 8; j++) {
        int e = e0 + 32 * j;
        v[j] = (e < n_edges);
        s[j] = v[j] ? src[e] : 0;
        d[j] = v[j] ? dst[e] : 0;
    }
    int p[8];
    #pragma unroll
    for (int j = 0; j < 8; j++)
        p[j] = v[j] ? atomicAdd(&g_cnt[d[j]], 1) : CAP;
    #pragma unroll
    for (int j = 0; j < 8; j++)
        if (v[j] && p[j] < CAP)
            g_bucket[d[j] * CAP + p[j]] = (unsigned short)s[j];
}

// ---------------- kernel: warp-per-node pull aggregation (inlined exact fallback) ----------------
__global__ void aggregate_kernel(const float* __restrict__ feat,
                                 const int* __restrict__ src,
                                 const int* __restrict__ dst,
                                 int n_nodes, int n_edges) {
    int w = (blockIdx.x * blockDim.x + threadIdx.x) >> 5;
    if (w >= MAX_NODES) return;
    int lane = threadIdx.x & 31;

    int c = g_cnt[w];
    float m0, m1, m2, m3;

    if (c <= CAP) {
        unsigned long long acc01 = 0ull, acc23 = 0ull;
        const uint2* fb = reinterpret_cast<const uint2*>(g_zh);
        const unsigned short* bk = &g_bucket[w * CAP];
        for (int i0 = 0; i0 < c; i0 += 32) {
            int take = min(32, c - i0);
            int my = (lane < take) ? (int)bk[i0 + lane] : 0;
            #pragma unroll 4
            for (int j = 0; j < take; j++) {
                int s = __shfl_sync(0xffffffffu, my, j);
                uint2 vv = __ldg(&fb[(size_t)s * 64 + lane]);
                addf32x2(acc01, bf2_to_f32x2(vv.x));
                addf32x2(acc23, bf2_to_f32x2(vv.y));
            }
        }
        float inv = 1.0f / fmaxf((float)c, 1.0f);
        unpack2(acc01, m0, m1);
        unpack2(acc23, m2, m3);
        m0 *= inv; m1 *= inv; m2 *= inv; m3 *= inv;
    } else {
        float a0 = 0.f, a1 = 0.f, a2 = 0.f, a3 = 0.f;
        const float4* f4 = reinterpret_cast<const float4*>(feat);
        for (int e = 0; e < n_edges; e++) {
            if (dst[e] == w) {
                float4 vv = f4[(size_t)src[e] * D4 + lane];
                a0 += vv.x; a1 += vv.y; a2 += vv.z; a3 += vv.w;
            }
        }
        float inv = 1.0f / (float)c;
        m0 = a0 * inv; m1 = a1 * inv; m2 = a2 * inv; m3 = a3 * inv;
    }

    __nv_bfloat16 h0 = __float2bfloat16_rn(m0);
    __nv_bfloat16 h1 = __float2bfloat16_rn(m1);
    __nv_bfloat16 h2 = __float2bfloat16_rn(m2);
    __nv_bfloat16 h3 = __float2bfloat16_rn(m3);
    __nv_bfloat162 hA = __halves2bfloat162(h0, h1);
    __nv_bfloat162 hB = __halves2bfloat162(h2, h3);
    __nv_bfloat162 lA = __floats2bfloat162_rn(m0 - __bfloat162float(h0),
                                              m1 - __bfloat162float(h1));
    __nv_bfloat162 lB = __floats2bfloat162_rn(m2 - __bfloat162float(h2),
                                              m3 - __bfloat162float(h3));
    uint2* zh = reinterpret_cast<uint2*>(g_zh);
    uint2* zl = reinterpret_cast<uint2*>(g_zl);
    zh[(size_t)w * 64 + 32 + lane] =
        make_uint2(*reinterpret_cast<unsigned int*>(&hA), *reinterpret_cast<unsigned int*>(&hB));
    zl[(size_t)w * 64 + 32 + lane] =
        make_uint2(*reinterpret_cast<unsigned int*>(&lA), *reinterpret_cast<unsigned int*>(&lB));
}

// ---------------- kernel: split-bf16 mma.sync GEMM, cp.async pipeline + 2 CTAs/SM ----------------
// Per CTA: 128 rows x 128 cols; K=256 in 8 chunks of 32; prefetch chunk c+1 during compute of c.
// acc += Zh*Wh + Zl*Wh + Zh*Wl. 8 warps: warp tile 64x32 = 4 m-tiles x 4 n-tiles of m16n8k16.
__global__ void __launch_bounds__(256, 2)
gemm_kernel(const float* __restrict__ b_self,
            const float* __restrict__ b_neigh,
            float* __restrict__ out,
            int n_nodes) {
    extern __shared__ char sm[];
    const uint32_t smb = smem_u32(sm);
    const int tid  = threadIdx.x;
    const int lane = tid & 31;
    const int wid  = tid >> 5;
    const int base = blockIdx.x * 128;

    const int wm = (wid & 1) * 64;
    const int wn = (wid >> 1) * 32;
    const int qr = lane >> 2;
    const int qc = lane & 3;

    if (tid < 128)
        *reinterpret_cast<float*>(sm + SM_BIAS + tid * 4) = b_self[tid] + b_neigh[tid];

    const uint4* zh4 = reinterpret_cast<const uint4*>(g_zh);
    const uint4* zl4 = reinterpret_cast<const uint4*>(g_zl);
    const uint4* wh4 = reinterpret_cast<const uint4*>(g_wh);
    const uint4* wl4 = reinterpret_cast<const uint4*>(g_wl);

    // stage one k-chunk (32 wide = 4 uint4/row) into buffer `buf` via cp.async
    auto stage = [&](int chunk, int buf) {
        uint32_t sb = smb + buf * BUF_B;
        #pragma unroll
        for (int i = tid; i < 512; i += 256) {
            int r = i >> 2;
            int c = i & 3;
            uint32_t so = r * ROWB + c * 16;
            size_t zi = (size_t)(base + r) * 32 + chunk * 4 + c;
            size_t wi = (size_t)r * 32 + chunk * 4 + c;
            cp16(sb + SM_AH + so, zh4 + zi);
            cp16(sb + SM_AL + so, zl4 + zi);
            cp16(sb + SM_BH + so, wh4 + wi);
            cp16(sb + SM_BL + so, wl4 + wi);
        }
    };

    float acc[4][4][4];
    #pragma unroll
    for (int mt = 0; mt < 4; mt++)
        #pragma unroll
        for (int nt = 0; nt < 4; nt++)
            #pragma unroll
            for (int r = 0; r < 4; r++) acc[mt][nt][r] = 0.f;

    stage(0, 0);
    CP_COMMIT();

    #pragma unroll 1
    for (int chunk = 0; chunk < 8; chunk++) {
        if (chunk + 1 < 8) {
            stage(chunk + 1, (chunk + 1) & 1);
            CP_COMMIT();
            CP_WAIT(1);                    // chunk's group complete; prefetch in flight
        } else {
            CP_WAIT(0);
        }
        __syncthreads();

        const char* sb = sm + (chunk & 1) * BUF_B;

        // --- 2 k-steps of 16 ---
        #pragma unroll
        for (int ks = 0; ks < 2; ks++) {
            int kb = ks * 32 + qc * 4;

            unsigned ah[4][4], al[4][4];
            #pragma unroll
            for (int mt = 0; mt < 4; mt++) {
                int r0 = (wm + mt * 16 + qr) * ROWB;
                int r8 = r0 + 8 * ROWB;
                ah[mt][0] = *reinterpret_cast<const unsigned*>(sb + SM_AH + r0 + kb);
                ah[mt][1] = *reinterpret_cast<const unsigned*>(sb + SM_AH + r8 + kb);
                ah[mt][2] = *reinterpret_cast<const unsigned*>(sb + SM_AH + r0 + kb + 16);
                ah[mt][3] = *reinterpret_cast<const unsigned*>(sb + SM_AH + r8 + kb + 16);
                al[mt][0] = *reinterpret_cast<const unsigned*>(sb + SM_AL + r0 + kb);
                al[mt][1] = *reinterpret_cast<const unsigned*>(sb + SM_AL + r8 + kb);
                al[mt][2] = *reinterpret_cast<const unsigned*>(sb + SM_AL + r0 + kb + 16);
                al[mt][3] = *reinterpret_cast<const unsigned*>(sb + SM_AL + r8 + kb + 16);
            }
            unsigned bh[4][2], bl[4][2];
            #pragma unroll
            for (int nt = 0; nt < 4; nt++) {
                int n0 = (wn + nt * 8 + qr) * ROWB;
                bh[nt][0] = *reinterpret_cast<const unsigned*>(sb + SM_BH + n0 + kb);
                bh[nt][1] = *reinterpret_cast<const unsigned*>(sb + SM_BH + n0 + kb + 16);
                bl[nt][0] = *reinterpret_cast<const unsigned*>(sb + SM_BL + n0 + kb);
                bl[nt][1] = *reinterpret_cast<const unsigned*>(sb + SM_BL + n0 + kb + 16);
            }

            #pragma unroll
            for (int mt = 0; mt < 4; mt++)
                #pragma unroll
                for (int nt = 0; nt < 4; nt++) {
                    mma_bf16(acc[mt][nt], ah[mt], bh[nt]);
                    mma_bf16(acc[mt][nt], al[mt], bh[nt]);
                    mma_bf16(acc[mt][nt], ah[mt], bl[nt]);
                }
        }
        __syncthreads();   // seal reads of this buffer before it is restaged
    }

    // --- epilogue: bias + direct float2 stores ---
    #pragma unroll
    for (int mt = 0; mt < 4; mt++) {
        int m0 = base + wm + mt * 16 + qr;
        #pragma unroll
        for (int nt = 0; nt < 4; nt++) {
            int n0 = wn + nt * 8 + 2 * qc;
            float2 bv = *reinterpret_cast<const float2*>(sm + SM_BIAS + n0 * 4);
            if (m0 < n_nodes)
                *reinterpret_cast<float2*>(out + (size_t)m0 * D + n0) =
                    make_float2(acc[mt][nt][0] + bv.x, acc[mt][nt][1] + bv.y);
            if (m0 + 8 < n_nodes)
                *reinterpret_cast<float2*>(out + (size_t)(m0 + 8) * D + n0) =
                    make_float2(acc[mt][nt][2] + bv.x, acc[mt][nt][3] + bv.y);
        }
    }
}

// ---------------- launch ----------------
extern "C" void kernel_launch(void* const* d_in, const int* in_sizes, int n_in,
                              void* d_out, int out_size) {
    const float* feat    = (const float*)d_in[0];
    const int*   src     = (const int*)  d_in[1];
    const int*   dst     = (const int*)  d_in[2];
    const float* W_self  = (const float*)d_in[3];
    const float* b_self  = (const float*)d_in[4];
    const float* W_neigh = (const float*)d_in[5];
    const float* b_neigh = (const float*)d_in[6];
    float* out = (float*)d_out;

    const int n_nodes = in_sizes[0] / D;
    const int n_edges = in_sizes[1];

    prep_kernel<<<(MAX_NODES * 64 + 255) / 256, 256>>>(feat, W_self, W_neigh, n_nodes * 64);

    {
        int warps = (n_edges + 255) / 256;
        int blocks = (warps * 32 + 255) / 256;
        fill_kernel<<<blocks, 256>>>(src, dst, n_edges);
    }

    {
        int blocks = (MAX_NODES + 7) / 8;
        aggregate_kernel<<<blocks, 256>>>(feat, src, dst, n_nodes, n_edges);
    }

    {
        cudaFuncSetAttribute(gemm_kernel,
                             cudaFuncAttributeMaxDynamicSharedMemorySize, SM_TOTAL);
        int blocks = MAX_NODES / 128;               // 391
        gemm_kernel<<<blocks, 256, SM_TOTAL>>>(b_self, b_neigh, out, n_nodes);
    }
}